// round 16
// baseline (speedup 1.0000x reference)
#include <cuda_runtime.h>

// out[i] = cos(x[i]) * cos(theta[i & 63])
// N = 33,554,432 fp32 -> 8,388,608 float4.
//
// R15 found a real win: 1024-thread CTAs -> 43.52us wall (vs 45.12-45.28
// seven-run band for 512-thread CTAs), with ncu kernel time unchanged —
// the gain is at natural clocks (fewer CTA streams/SM, regs 30->22).
// This round isolates the mechanism: 1024 threads with UNROLL=4 (MLP=4,
// CHUNK=4096, 2048 blocks). If the win persists/stacks -> wide CTA is the
// cause; if it reverts -> the low-register UNROLL=2 shape was the cause.
// Per-thread inner stride = 1024 float4 = 4096 floats == 0 mod 64, so each
// thread's theta vector is invariant across its 4 iterations.

#define THREADS 1024
#define UNROLL  4
#define CHUNK   (THREADS * UNROLL)     // 4096 float4 per block

__global__ void __launch_bounds__(THREADS) qab_kernel(
    const float4* __restrict__ x4,
    const float* __restrict__ theta,
    float4* __restrict__ out4,
    int nvec)
{
    __shared__ float ct[64];
    if (threadIdx.x < 64) {
        ct[threadIdx.x] = cosf(theta[threadIdx.x]);   // accurate; 64 values
    }
    __syncthreads();

    const int base = blockIdx.x * CHUNK + threadIdx.x;
    const int t = (base << 2) & 63;                    // 16B-aligned theta slot
    const float4 c = *reinterpret_cast<const float4*>(&ct[t]);

    if (base + (UNROLL - 1) * THREADS < nvec) {
        // Front-batch all 4 LDG.128 (MLP=4)
        float4 v[UNROLL];
        #pragma unroll
        for (int k = 0; k < UNROLL; k++)
            v[k] = x4[base + k * THREADS];

        #pragma unroll
        for (int k = 0; k < UNROLL; k++) {
            float4 r;
            r.x = __cosf(v[k].x) * c.x;
            r.y = __cosf(v[k].y) * c.y;
            r.z = __cosf(v[k].z) * c.z;
            r.w = __cosf(v[k].w) * c.w;
            out4[base + k * THREADS] = r;
        }
    } else {
        // Tail path (unused for the shipped shape; kept for generality)
        #pragma unroll
        for (int k = 0; k < UNROLL; k++) {
            int i = base + k * THREADS;
            if (i < nvec) {
                float4 v = x4[i];
                float4 r;
                r.x = __cosf(v.x) * c.x;
                r.y = __cosf(v.y) * c.y;
                r.z = __cosf(v.z) * c.z;
                r.w = __cosf(v.w) * c.w;
                out4[i] = r;
            }
        }
    }
}

extern "C" void kernel_launch(void* const* d_in, const int* in_sizes, int n_in,
                              void* d_out, int out_size)
{
    const float* x     = (const float*)d_in[0];
    const float* theta = (const float*)d_in[1];
    float* out         = (float*)d_out;

    int n    = out_size;          // total elements (33,554,432)
    int nvec = n >> 2;            // float4 count (8,388,608)

    int blocks = (nvec + CHUNK - 1) / CHUNK;   // 2048 for the shipped shape

    qab_kernel<<<blocks, THREADS>>>(
        (const float4*)x, theta, (float4*)out, nvec);
}

// round 17
// speedup vs baseline: 1.0021x; 1.0021x over previous
#include <cuda_runtime.h>

// out[i] = cos(x[i]) * cos(theta[i & 63])
// N = 33,554,432 fp32 -> 8,388,608 float4.
//
// Mechanism isolation (R15 won at 43.5us with 1024thr/UNROLL=2; R16 showed
// 1024thr/UNROLL=4 reverts to 45.1us): the variable is MLP_p1 (front-batched
// LDG count per thread), per the B300 multi-CTA spread model
// spr_max ~ f(oe * MLP_p1) — cross-CTA L1tex-queue contention. MLP_p1=2
// still keeps 64KB in-flight per SM (4x latency-BW product).
// This round: 512 threads, UNROLL=2 (CHUNK=1024, 8192 blocks). If dur ~43.5,
// MLP_p1 is confirmed and block size is irrelevant.
// Per-thread inner stride = 512 float4 = 2048 floats == 0 mod 64, so each
// thread's theta vector is invariant across its 2 iterations.

#define THREADS 512
#define UNROLL  2
#define CHUNK   (THREADS * UNROLL)     // 1024 float4 per block

__global__ void __launch_bounds__(THREADS) qab_kernel(
    const float4* __restrict__ x4,
    const float* __restrict__ theta,
    float4* __restrict__ out4,
    int nvec)
{
    __shared__ float ct[64];
    if (threadIdx.x < 64) {
        ct[threadIdx.x] = cosf(theta[threadIdx.x]);   // accurate; 64 values
    }
    __syncthreads();

    const int base = blockIdx.x * CHUNK + threadIdx.x;
    const int t = (base << 2) & 63;                    // 16B-aligned theta slot
    const float4 c = *reinterpret_cast<const float4*>(&ct[t]);

    if (base + (UNROLL - 1) * THREADS < nvec) {
        // Front-batch both LDG.128 (MLP_p1=2)
        float4 v[UNROLL];
        #pragma unroll
        for (int k = 0; k < UNROLL; k++)
            v[k] = x4[base + k * THREADS];

        #pragma unroll
        for (int k = 0; k < UNROLL; k++) {
            float4 r;
            r.x = __cosf(v[k].x) * c.x;
            r.y = __cosf(v[k].y) * c.y;
            r.z = __cosf(v[k].z) * c.z;
            r.w = __cosf(v[k].w) * c.w;
            out4[base + k * THREADS] = r;
        }
    } else {
        // Tail path (unused for the shipped shape; kept for generality)
        #pragma unroll
        for (int k = 0; k < UNROLL; k++) {
            int i = base + k * THREADS;
            if (i < nvec) {
                float4 v = x4[i];
                float4 r;
                r.x = __cosf(v.x) * c.x;
                r.y = __cosf(v.y) * c.y;
                r.z = __cosf(v.z) * c.z;
                r.w = __cosf(v.w) * c.w;
                out4[i] = r;
            }
        }
    }
}

extern "C" void kernel_launch(void* const* d_in, const int* in_sizes, int n_in,
                              void* d_out, int out_size)
{
    const float* x     = (const float*)d_in[0];
    const float* theta = (const float*)d_in[1];
    float* out         = (float*)d_out;

    int n    = out_size;          // total elements (33,554,432)
    int nvec = n >> 2;            // float4 count (8,388,608)

    int blocks = (nvec + CHUNK - 1) / CHUNK;   // 8192 for the shipped shape

    qab_kernel<<<blocks, THREADS>>>(
        (const float4*)x, theta, (float4*)out, nvec);
}